// round 3
// baseline (speedup 1.0000x reference)
#include <cuda_runtime.h>
#include <math.h>

// Problem constants
#define TAU   0.07f
#define BB    8
#define CC    128
#define HH    512
#define WW    512
#define HWSZ  (HH*WW)
#define KK    64
#define NNEG  7
#define PP    4096
#define NQ    (BB*KK)          // 512
#define CPAD  68               // pool smem row stride (words)

// Device scratch (allocation-free)
__device__ float g_pinv[PP];            // pool inverse L2 norms
__device__ float g_q_norm[NQ * CC];     // normalized queries [NQ][C]
__device__ float g_pmax_val[NQ * 64];   // per (query, pool-block) max sim
__device__ int   g_pmax_idx[NQ * 64];
__device__ float g_partial[64];
__device__ int   g_done;

__device__ __forceinline__ void ffma2(unsigned long long& d,
                                      unsigned long long a,
                                      unsigned long long b) {
    asm("fma.rn.f32x2 %0, %1, %2, %0;" : "+l"(d) : "l"(a), "l"(b));
}

// ---------------------------------------------------------------------------
// Kernel 1: prep — pool inverse norms (blocks 0..511, warp per row, 8 rows/blk)
//                  queries gather+normalize (blocks 512..575, warp per query)
//                  + reset g_done ticket (graph-replay safe)
// ---------------------------------------------------------------------------
__global__ void __launch_bounds__(256)
prep_kernel(const float* __restrict__ pool,
            const float* __restrict__ qf,
            const int*   __restrict__ qidx) {
    int t = threadIdx.x;
    int w = t >> 5, lane = t & 31;
    if (blockIdx.x == 0 && t == 0) g_done = 0;

    if (blockIdx.x < 512) {
        // pool row r: sum of squares -> inverse norm
        int r = blockIdx.x * 8 + w;
        float4 v = ((const float4*)pool)[r * 32 + lane];
        float ss = v.x*v.x + v.y*v.y + v.z*v.z + v.w*v.w;
        #pragma unroll
        for (int o = 16; o > 0; o >>= 1) ss += __shfl_xor_sync(0xFFFFFFFFu, ss, o);
        if (lane == 0) g_pinv[r] = 1.0f / fmaxf(sqrtf(ss), 1e-12f);
    } else {
        // query qb: gather 128 strided channels, normalize, store
        int qb = (blockIdx.x - 512) * 8 + w;
        int b = qb >> 6, k = qb & 63;
        int idx = qidx[b * KK + k];
        float v[4]; float ss = 0.f;
        #pragma unroll
        for (int j = 0; j < 4; j++) {
            int c = lane * 4 + j;
            v[j] = qf[(long)(b * CC + c) * HWSZ + idx];
            ss += v[j] * v[j];
        }
        #pragma unroll
        for (int o = 16; o > 0; o >>= 1) ss += __shfl_xor_sync(0xFFFFFFFFu, ss, o);
        float inv = 1.0f / fmaxf(sqrtf(ss), 1e-12f);
        float4 nv = make_float4(v[0]*inv, v[1]*inv, v[2]*inv, v[3]*inv);
        ((float4*)(g_q_norm + qb * CC))[lane] = nv;
    }
}

// ---------------------------------------------------------------------------
// Kernel 2: tiled GEMM + per-tile argmax, packed f32x2 FMA.
// grid = (64 pool-blocks, 8 query-blocks), 256 threads.
// Block tile: 64 q x 64 p; thread micro-tile 4x4; K in two 64-ch chunks.
// ---------------------------------------------------------------------------
__global__ void __launch_bounds__(256, 3)
main_gemm_kernel(const float* __restrict__ pool) {
    __shared__ float q_s[64 * 64];
    __shared__ float p_s[64 * CPAD];

    int t = threadIdx.x;
    int tx = t & 15, ty = t >> 4;
    int pblk = blockIdx.x, qblk = blockIdx.y;
    int qbase = qblk * 64, pbase = pblk * 64;

    unsigned long long acc2[4][4];
    #pragma unroll
    for (int i = 0; i < 4; i++)
        #pragma unroll
        for (int j = 0; j < 4; j++) acc2[i][j] = 0ULL;

    for (int kc = 0; kc < 2; kc++) {
        if (kc) __syncthreads();
        #pragma unroll
        for (int it = 0; it < 4; it++) {
            int idx = t + it * 256;
            int r = idx >> 4;          // 0..63
            int c4 = idx & 15;         // 0..15
            float4 v = ((const float4*)g_q_norm)[(qbase + r) * 32 + kc * 16 + c4];
            *(float4*)(q_s + r * 64 + c4 * 4) = v;
            float4 u = ((const float4*)pool)[(pbase + r) * 32 + kc * 16 + c4];
            float s = g_pinv[pbase + r];
            u.x *= s; u.y *= s; u.z *= s; u.w *= s;
            *(float4*)(p_s + r * CPAD + c4 * 4) = u;
        }
        __syncthreads();

        #pragma unroll
        for (int c4 = 0; c4 < 16; c4++) {
            union F4 { float4 f; unsigned long long u[2]; } qv[4], pv[4];
            #pragma unroll
            for (int qi = 0; qi < 4; qi++)
                qv[qi].f = *(const float4*)(q_s + (ty * 4 + qi) * 64 + c4 * 4);
            #pragma unroll
            for (int pj = 0; pj < 4; pj++)
                pv[pj].f = *(const float4*)(p_s + (tx + 16 * pj) * CPAD + c4 * 4);
            #pragma unroll
            for (int qi = 0; qi < 4; qi++)
                #pragma unroll
                for (int pj = 0; pj < 4; pj++) {
                    ffma2(acc2[qi][pj], qv[qi].u[0], pv[pj].u[0]);
                    ffma2(acc2[qi][pj], qv[qi].u[1], pv[pj].u[1]);
                }
        }
    }

    // collapse packed halves -> dot, per-thread argmax over 4 pool rows
    float bv[4]; int bi[4];
    #pragma unroll
    for (int qi = 0; qi < 4; qi++) {
        bv[qi] = -1e30f; bi[qi] = 0;
        #pragma unroll
        for (int pj = 0; pj < 4; pj++) {
            float2 d = *(float2*)&acc2[qi][pj];
            float dot = d.x + d.y;
            int p = pbase + tx + 16 * pj;
            if (dot > bv[qi] || (dot == bv[qi] && p < bi[qi])) { bv[qi] = dot; bi[qi] = p; }
        }
    }
    // reduce over the 16 tx lanes (xor stays within 16-lane half-warps)
    #pragma unroll
    for (int o = 8; o > 0; o >>= 1) {
        #pragma unroll
        for (int qi = 0; qi < 4; qi++) {
            float ov = __shfl_xor_sync(0xFFFFFFFFu, bv[qi], o);
            int   oi = __shfl_xor_sync(0xFFFFFFFFu, bi[qi], o);
            if (ov > bv[qi] || (ov == bv[qi] && oi < bi[qi])) { bv[qi] = ov; bi[qi] = oi; }
        }
    }
    if (tx == 0) {
        #pragma unroll
        for (int qi = 0; qi < 4; qi++) {
            int q = qbase + ty * 4 + qi;
            g_pmax_val[q * 64 + pblk] = bv[qi];
            g_pmax_idx[q * 64 + pblk] = bi[qi];
        }
    }
}

// ---------------------------------------------------------------------------
// Kernel 3: finalize — warp per query (argmax over 64 partials, negatives,
// softmax-CE), block partial sum, deterministic last-block final mean.
// grid = 64 x 256
// ---------------------------------------------------------------------------
__global__ void __launch_bounds__(256)
finalize_kernel(const float* __restrict__ negs, float* __restrict__ out) {
    __shared__ float loss_sm[8];
    int t = threadIdx.x, w = t >> 5, lane = t & 31;
    int q = blockIdx.x * 8 + w;
    int b = q >> 6, k = q & 63;

    // argmax over 64 per-block partials
    float v1 = g_pmax_val[q * 64 + lane];
    int   i1 = g_pmax_idx[q * 64 + lane];
    float v2 = g_pmax_val[q * 64 + 32 + lane];
    int   i2 = g_pmax_idx[q * 64 + 32 + lane];
    if (v2 > v1 || (v2 == v1 && i2 < i1)) { v1 = v2; i1 = i2; }
    #pragma unroll
    for (int o = 16; o > 0; o >>= 1) {
        float ov = __shfl_xor_sync(0xFFFFFFFFu, v1, o);
        int   oi = __shfl_xor_sync(0xFFFFFFFFu, i1, o);
        if (ov > v1 || (ov == v1 && oi < i1)) { v1 = ov; i1 = oi; }
    }

    float l[1 + NNEG];
    l[0] = v1 / TAU;

    float4 qv = ((const float4*)(g_q_norm + q * CC))[lane];
    #pragma unroll
    for (int n = 0; n < NNEG; n++) {
        const float4* np = (const float4*)(negs + (((long)(b * KK + k)) * NNEG + n) * CC);
        float4 nv = np[lane];
        float ss = nv.x*nv.x + nv.y*nv.y + nv.z*nv.z + nv.w*nv.w;
        float dt = nv.x*qv.x + nv.y*qv.y + nv.z*qv.z + nv.w*qv.w;
        #pragma unroll
        for (int o = 16; o > 0; o >>= 1) {
            ss += __shfl_xor_sync(0xFFFFFFFFu, ss, o);
            dt += __shfl_xor_sync(0xFFFFFFFFu, dt, o);
        }
        l[n + 1] = (dt / fmaxf(sqrtf(ss), 1e-12f)) / TAU;
    }
    if (lane == 0) {
        float m = l[0];
        #pragma unroll
        for (int i = 1; i <= NNEG; i++) m = fmaxf(m, l[i]);
        float sum = 0.0f;
        #pragma unroll
        for (int i = 0; i <= NNEG; i++) sum += expf(l[i] - m);
        loss_sm[w] = m + logf(sum) - l[0];
    }
    __syncthreads();

    if (t == 0) {
        float s = 0.0f;
        #pragma unroll
        for (int i = 0; i < 8; i++) s += loss_sm[i];
        g_partial[blockIdx.x] = s;
        __threadfence();
        int ticket = atomicAdd(&g_done, 1);
        if (ticket == 63) {
            // last block finishes: fixed-order sum -> deterministic
            float tot = 0.0f;
            #pragma unroll
            for (int i = 0; i < 64; i++) tot += g_partial[i];
            out[0] = tot / (float)NQ;
        }
    }
}

extern "C" void kernel_launch(void* const* d_in, const int* in_sizes, int n_in,
                              void* d_out, int out_size) {
    const float* query_feat = (const float*)d_in[0];
    const float* pos_pool   = (const float*)d_in[1];
    const float* neg_protos = (const float*)d_in[2];
    const int*   query_idx  = (const int*)d_in[3];
    float* out = (float*)d_out;

    prep_kernel<<<576, 256>>>(pos_pool, query_feat, query_idx);
    dim3 grid(64, 8);
    main_gemm_kernel<<<grid, 256>>>(pos_pool);
    finalize_kernel<<<64, 256>>>(neg_protos, out);
}

// round 4
// speedup vs baseline: 1.0703x; 1.0703x over previous
#include <cuda_runtime.h>
#include <math.h>

// Problem constants
#define TAU   0.07f
#define BB    8
#define CC    128
#define HH    512
#define WW    512
#define HWSZ  (HH*WW)
#define KK    64
#define NNEG  7
#define PP    4096
#define NQ    (BB*KK)          // 512
#define CPAD  68               // pool smem row stride (words)

// Device scratch (allocation-free)
__device__ float g_q_norm[NQ * CC];     // normalized queries [NQ][C]
__device__ float g_pmax_val[NQ * 64];   // per (query, pool-block) max sim
__device__ float g_partial[64];
__device__ int   g_done;

__device__ __forceinline__ void ffma2(unsigned long long& d,
                                      unsigned long long a,
                                      unsigned long long b) {
    asm("fma.rn.f32x2 %0, %1, %2, %0;" : "+l"(d) : "l"(a), "l"(b));
}

// ---------------------------------------------------------------------------
// Kernel 1: prep — query gather+normalize only. 256 blocks x 256 threads,
// 2 queries per block, thread = channel (max MLP for the scattered gather).
// Also resets the g_done ticket (graph-replay safe).
// ---------------------------------------------------------------------------
__global__ void __launch_bounds__(256)
prep_kernel(const float* __restrict__ qf, const int* __restrict__ qidx) {
    __shared__ float sred[2][4];
    __shared__ float sinv[2];
    int t = threadIdx.x;
    if (blockIdx.x == 0 && t == 0) g_done = 0;

    int half = t >> 7;                 // which query in this block
    int c = t & 127;
    int qb = blockIdx.x * 2 + half;
    int b = qb >> 6, k = qb & 63;
    int idx = qidx[b * KK + k];
    float v = qf[(long)(b * CC + c) * HWSZ + idx];
    float ss = v * v;
    #pragma unroll
    for (int o = 16; o > 0; o >>= 1) ss += __shfl_xor_sync(0xFFFFFFFFu, ss, o);
    if ((t & 31) == 0) sred[half][(t >> 5) & 3] = ss;
    __syncthreads();
    if ((t & 127) == 0) {
        float s = sred[half][0] + sred[half][1] + sred[half][2] + sred[half][3];
        sinv[half] = 1.0f / fmaxf(sqrtf(s), 1e-12f);
    }
    __syncthreads();
    g_q_norm[qb * CC + c] = v * sinv[half];
}

// ---------------------------------------------------------------------------
// Kernel 2: tiled GEMM + per-tile max (values only), packed f32x2 FMA.
// grid = (64 pool-blocks, 8 query-blocks), 128 threads.
// Tile 64q x 64p; micro-tile 8q x 4p (tx 0..15 -> pool cols, ty 0..7 -> q rows).
// Pool staged RAW; per-row inverse norms computed in-block from smem and
// applied to the dots at the epilogue (dot(q, p/|p|) = dot(q,p)/|p|).
// ---------------------------------------------------------------------------
__global__ void __launch_bounds__(128)
main_gemm_kernel(const float* __restrict__ pool) {
    __shared__ float q_s[64 * 64];
    __shared__ float p_s[64 * CPAD];
    __shared__ float invp_s[64];

    int t = threadIdx.x;
    int tx = t & 15, ty = t >> 4;      // ty 0..7
    int pblk = blockIdx.x, qblk = blockIdx.y;
    int qbase = qblk * 64, pbase = pblk * 64;

    unsigned long long acc2[8][4];
    #pragma unroll
    for (int i = 0; i < 8; i++)
        #pragma unroll
        for (int j = 0; j < 4; j++) acc2[i][j] = 0ULL;

    float pss = 0.0f;                  // sumsq partial for pool row t>>1

    for (int kc = 0; kc < 2; kc++) {
        if (kc) __syncthreads();
        // stage 64x64-channel chunks: 1024 float4 each, 8 per thread
        #pragma unroll
        for (int it = 0; it < 8; it++) {
            int idx = t + it * 128;
            int r = idx >> 4;          // 0..63
            int c4 = idx & 15;         // 0..15
            float4 v = ((const float4*)g_q_norm)[(qbase + r) * 32 + kc * 16 + c4];
            *(float4*)(q_s + r * 64 + c4 * 4) = v;
            float4 u = ((const float4*)pool)[(pbase + r) * 32 + kc * 16 + c4];
            *(float4*)(p_s + r * CPAD + c4 * 4) = u;
        }
        __syncthreads();

        // pool row sumsq: 2 threads per row (t>>1), 8 float4 each half
        {
            int r = t >> 1, h = t & 1;
            float s = 0.0f;
            #pragma unroll
            for (int j = 0; j < 8; j++) {
                float4 u = *(const float4*)(p_s + r * CPAD + (h * 8 + j) * 4);
                s += u.x*u.x + u.y*u.y + u.z*u.z + u.w*u.w;
            }
            pss += s + __shfl_xor_sync(0xFFFFFFFFu, s, 1);
        }

        // MMA: 8q x 4p micro-tile, packed f32x2
        #pragma unroll
        for (int c4 = 0; c4 < 16; c4++) {
            union F4 { float4 f; unsigned long long u[2]; } qv[8], pv[4];
            #pragma unroll
            for (int qi = 0; qi < 8; qi++)
                qv[qi].f = *(const float4*)(q_s + (ty * 8 + qi) * 64 + c4 * 4);
            #pragma unroll
            for (int pj = 0; pj < 4; pj++)
                pv[pj].f = *(const float4*)(p_s + (tx + 16 * pj) * CPAD + c4 * 4);
            #pragma unroll
            for (int qi = 0; qi < 8; qi++)
                #pragma unroll
                for (int pj = 0; pj < 4; pj++) {
                    ffma2(acc2[qi][pj], qv[qi].u[0], pv[pj].u[0]);
                    ffma2(acc2[qi][pj], qv[qi].u[1], pv[pj].u[1]);
                }
        }
    }

    // inverse pool norms (both pair threads hold the full sumsq)
    if ((t & 1) == 0) invp_s[t >> 1] = 1.0f / fmaxf(sqrtf(pss), 1e-12f);
    __syncthreads();

    // epilogue: scale dots by inv|p|, max over this thread's 4 p rows
    float inv[4];
    #pragma unroll
    for (int pj = 0; pj < 4; pj++) inv[pj] = invp_s[tx + 16 * pj];

    float bv[8];
    #pragma unroll
    for (int qi = 0; qi < 8; qi++) {
        bv[qi] = -1e30f;
        #pragma unroll
        for (int pj = 0; pj < 4; pj++) {
            float2 d = *(float2*)&acc2[qi][pj];
            float dot = (d.x + d.y) * inv[pj];
            bv[qi] = fmaxf(bv[qi], dot);
        }
    }
    // max-reduce over the 16 tx lanes (xor stays within 16-lane groups)
    #pragma unroll
    for (int o = 8; o > 0; o >>= 1) {
        #pragma unroll
        for (int qi = 0; qi < 8; qi++)
            bv[qi] = fmaxf(bv[qi], __shfl_xor_sync(0xFFFFFFFFu, bv[qi], o));
    }
    if (tx == 0) {
        #pragma unroll
        for (int qi = 0; qi < 8; qi++)
            g_pmax_val[(qbase + ty * 8 + qi) * 64 + pblk] = bv[qi];
    }
}

// ---------------------------------------------------------------------------
// Kernel 3: finalize — warp per query (max over 64 partials, negatives,
// softmax-CE), block partial, deterministic last-block mean. grid = 64 x 256.
// ---------------------------------------------------------------------------
__global__ void __launch_bounds__(256)
finalize_kernel(const float* __restrict__ negs, float* __restrict__ out) {
    __shared__ float loss_sm[8];
    int t = threadIdx.x, w = t >> 5, lane = t & 31;
    int q = blockIdx.x * 8 + w;
    int b = q >> 6, k = q & 63;

    float v1 = fmaxf(g_pmax_val[q * 64 + lane], g_pmax_val[q * 64 + 32 + lane]);
    #pragma unroll
    for (int o = 16; o > 0; o >>= 1)
        v1 = fmaxf(v1, __shfl_xor_sync(0xFFFFFFFFu, v1, o));

    float l[1 + NNEG];
    l[0] = v1 / TAU;

    float4 qv = ((const float4*)(g_q_norm + q * CC))[lane];
    #pragma unroll
    for (int n = 0; n < NNEG; n++) {
        const float4* np = (const float4*)(negs + (((long)(b * KK + k)) * NNEG + n) * CC);
        float4 nv = np[lane];
        float ss = nv.x*nv.x + nv.y*nv.y + nv.z*nv.z + nv.w*nv.w;
        float dt = nv.x*qv.x + nv.y*qv.y + nv.z*qv.z + nv.w*qv.w;
        #pragma unroll
        for (int o = 16; o > 0; o >>= 1) {
            ss += __shfl_xor_sync(0xFFFFFFFFu, ss, o);
            dt += __shfl_xor_sync(0xFFFFFFFFu, dt, o);
        }
        l[n + 1] = (dt / fmaxf(sqrtf(ss), 1e-12f)) / TAU;
    }
    if (lane == 0) {
        float m = l[0];
        #pragma unroll
        for (int i = 1; i <= NNEG; i++) m = fmaxf(m, l[i]);
        float sum = 0.0f;
        #pragma unroll
        for (int i = 0; i <= NNEG; i++) sum += expf(l[i] - m);
        loss_sm[w] = m + logf(sum) - l[0];
    }
    __syncthreads();

    if (t == 0) {
        float s = 0.0f;
        #pragma unroll
        for (int i = 0; i < 8; i++) s += loss_sm[i];
        g_partial[blockIdx.x] = s;
        __threadfence();
        int ticket = atomicAdd(&g_done, 1);
        if (ticket == 63) {
            float tot = 0.0f;
            #pragma unroll
            for (int i = 0; i < 64; i++) tot += g_partial[i];
            out[0] = tot / (float)NQ;
        }
    }
}

extern "C" void kernel_launch(void* const* d_in, const int* in_sizes, int n_in,
                              void* d_out, int out_size) {
    const float* query_feat = (const float*)d_in[0];
    const float* pos_pool   = (const float*)d_in[1];
    const float* neg_protos = (const float*)d_in[2];
    const int*   query_idx  = (const int*)d_in[3];
    float* out = (float*)d_out;

    prep_kernel<<<256, 256>>>(query_feat, query_idx);
    dim3 grid(64, 8);
    main_gemm_kernel<<<grid, 128>>>(pos_pool);
    finalize_kernel<<<64, 256>>>(neg_protos, out);
}